// round 1
// baseline (speedup 1.0000x reference)
#include <cuda_runtime.h>
#include <math.h>

#define BATCH 4
#define CDIM 128
#define HWDIM 4096
#define NGROUP 8
#define CPG 16
#define NH 4
#define HD 32
#define OC 384   // 3*C

// Scratch (allocation-free: device globals)
__device__ float g_xn[BATCH * CDIM * HWDIM];    // 8 MB  groupnorm output (also residual)
__device__ float g_qkv[BATCH * OC * HWDIM];     // 24 MB qkv projections
__device__ float g_att[BATCH * CDIM * HWDIM];   // 8 MB  attention output
__device__ float g_mean[BATCH * NGROUP];
__device__ float g_rstd[BATCH * NGROUP];

// ---------------------------------------------------------------------------
// 1. GroupNorm statistics: one block per (b, g); group data is contiguous
//    (16 channels x 4096) = 65536 floats.
// ---------------------------------------------------------------------------
__global__ void gn_stats_kernel(const float* __restrict__ x) {
    int bg = blockIdx.x;  // 0..31
    const float4* p = reinterpret_cast<const float4*>(x + (size_t)bg * CPG * HWDIM);
    const int n4 = CPG * HWDIM / 4;  // 16384
    float s = 0.f, ss = 0.f;
    for (int i = threadIdx.x; i < n4; i += blockDim.x) {
        float4 v = p[i];
        s  += v.x + v.y + v.z + v.w;
        ss += v.x * v.x + v.y * v.y + v.z * v.z + v.w * v.w;
    }
    __shared__ float sh_s[256], sh_ss[256];
    sh_s[threadIdx.x] = s;
    sh_ss[threadIdx.x] = ss;
    __syncthreads();
    for (int off = 128; off > 0; off >>= 1) {
        if (threadIdx.x < off) {
            sh_s[threadIdx.x]  += sh_s[threadIdx.x + off];
            sh_ss[threadIdx.x] += sh_ss[threadIdx.x + off];
        }
        __syncthreads();
    }
    if (threadIdx.x == 0) {
        const float inv = 1.0f / (float)(CPG * HWDIM);
        float mean = sh_s[0] * inv;
        float var  = sh_ss[0] * inv - mean * mean;
        g_mean[bg] = mean;
        g_rstd[bg] = rsqrtf(var + 1e-5f);
    }
}

// ---------------------------------------------------------------------------
// 2. Apply GroupNorm: xn = (x - mean) * rstd * w + b  (vectorized float4)
// ---------------------------------------------------------------------------
__global__ void gn_apply_kernel(const float* __restrict__ x,
                                const float* __restrict__ w,
                                const float* __restrict__ bias) {
    int i4 = blockIdx.x * blockDim.x + threadIdx.x;
    const int total4 = BATCH * CDIM * HWDIM / 4;
    if (i4 >= total4) return;
    int e  = i4 * 4;
    int c  = (e / HWDIM) % CDIM;
    int bg = e / (CPG * HWDIM);
    float mean = g_mean[bg], rstd = g_rstd[bg];
    float sw = w[c] * rstd;
    float sb = bias[c] - mean * sw;
    float4 v = reinterpret_cast<const float4*>(x)[i4];
    float4 o;
    o.x = v.x * sw + sb;
    o.y = v.y * sw + sb;
    o.z = v.z * sw + sb;
    o.w = v.w * sw + sb;
    reinterpret_cast<float4*>(g_xn)[i4] = o;
}

// ---------------------------------------------------------------------------
// 3/5. Batched GEMM: Out[b,o,t] = sum_c W[o,c] * X[b,c,t] + bias[o] (+ resid)
//      64x64 block tile, BK=16, 256 threads, 4x4 micro-tile per thread.
// ---------------------------------------------------------------------------
template <int OTOT, bool RESID>
__global__ void __launch_bounds__(256) gemm_kernel(const float* __restrict__ W,
                                                   const float* __restrict__ bias,
                                                   const float* __restrict__ X,
                                                   float* __restrict__ Out,
                                                   const float* __restrict__ resid) {
    int b = blockIdx.z;
    const float* Xb = X + (size_t)b * CDIM * HWDIM;
    float* Ob = Out + (size_t)b * OTOT * HWDIM;
    int o0 = blockIdx.y * 64;
    int t0 = blockIdx.x * 64;
    __shared__ float As[16][64];
    __shared__ float Bs[16][68];
    float acc[4][4];
#pragma unroll
    for (int i = 0; i < 4; i++)
#pragma unroll
        for (int j = 0; j < 4; j++) acc[i][j] = 0.f;

    int tid = threadIdx.x;
    int tx = tid & 15, ty = tid >> 4;

    for (int k0 = 0; k0 < CDIM; k0 += 16) {
#pragma unroll 4
        for (int i = tid; i < 64 * 16; i += 256) {
            int o = i >> 4, k = i & 15;
            As[k][o] = W[(size_t)(o0 + o) * CDIM + k0 + k];
        }
#pragma unroll 4
        for (int i = tid; i < 16 * 64; i += 256) {
            int k = i >> 6, t = i & 63;
            Bs[k][t] = Xb[(size_t)(k0 + k) * HWDIM + t0 + t];
        }
        __syncthreads();
#pragma unroll
        for (int k = 0; k < 16; k++) {
            float a[4], bb[4];
#pragma unroll
            for (int i = 0; i < 4; i++) a[i] = As[k][ty * 4 + i];
#pragma unroll
            for (int j = 0; j < 4; j++) bb[j] = Bs[k][tx * 4 + j];
#pragma unroll
            for (int i = 0; i < 4; i++)
#pragma unroll
                for (int j = 0; j < 4; j++) acc[i][j] += a[i] * bb[j];
        }
        __syncthreads();
    }

#pragma unroll
    for (int i = 0; i < 4; i++) {
        int o = o0 + ty * 4 + i;
        float bo = bias[o];
#pragma unroll
        for (int j = 0; j < 4; j++) {
            int t = t0 + tx * 4 + j;
            float v = acc[i][j] + bo;
            if (RESID) v += resid[(size_t)b * CDIM * HWDIM + (size_t)o * HWDIM + t];
            Ob[(size_t)o * HWDIM + t] = v;
        }
    }
}

// ---------------------------------------------------------------------------
// 4. Flash attention. One (b,h) per blockIdx.{z,y}; 128 queries per block,
//    one query per thread; stream keys/values in 64-wide smem tiles.
// ---------------------------------------------------------------------------
__global__ void __launch_bounds__(128) attn_kernel(const float* __restrict__ qkv,
                                                   float* __restrict__ att) {
    int b = blockIdx.z, h = blockIdx.y;
    int qi = blockIdx.x * 128 + threadIdx.x;
    const float* Qb = qkv + ((size_t)b * OC + h * HD) * HWDIM;
    const float* Kb = Qb + (size_t)CDIM * HWDIM;
    const float* Vb = Qb + (size_t)2 * CDIM * HWDIM;
    const float scale = 0.088388347648318447f;  // 128^-0.5

    float q[HD];
#pragma unroll
    for (int c = 0; c < HD; c++) q[c] = Qb[(size_t)c * HWDIM + qi] * scale;

    float m = -1e30f, l = 0.f;
    float acc[HD];
#pragma unroll
    for (int c = 0; c < HD; c++) acc[c] = 0.f;

    __shared__ float4 sk[HD][16];  // 32 x 64 floats = 8 KB
    __shared__ float4 sv[HD][16];  // 8 KB

    for (int j0 = 0; j0 < HWDIM; j0 += 64) {
        __syncthreads();
#pragma unroll
        for (int i = threadIdx.x; i < HD * 64; i += 128) {
            int c = i >> 6, j = i & 63;
            reinterpret_cast<float*>(sk[c])[j] = Kb[(size_t)c * HWDIM + j0 + j];
            reinterpret_cast<float*>(sv[c])[j] = Vb[(size_t)c * HWDIM + j0 + j];
        }
        __syncthreads();

        float s[64];
#pragma unroll
        for (int j = 0; j < 64; j++) s[j] = 0.f;
#pragma unroll
        for (int c = 0; c < HD; c++) {
            float qc = q[c];
#pragma unroll
            for (int j4 = 0; j4 < 16; j4++) {
                float4 kv = sk[c][j4];
                s[4 * j4 + 0] += qc * kv.x;
                s[4 * j4 + 1] += qc * kv.y;
                s[4 * j4 + 2] += qc * kv.z;
                s[4 * j4 + 3] += qc * kv.w;
            }
        }

        float mt = m;
#pragma unroll
        for (int j = 0; j < 64; j++) mt = fmaxf(mt, s[j]);
        float corr = __expf(m - mt);
        m = mt;
        float lsum = 0.f;
#pragma unroll
        for (int j = 0; j < 64; j++) {
            s[j] = __expf(s[j] - mt);
            lsum += s[j];
        }
        l = l * corr + lsum;
#pragma unroll
        for (int c = 0; c < HD; c++) acc[c] *= corr;
#pragma unroll
        for (int c = 0; c < HD; c++) {
            float a = acc[c];
#pragma unroll
            for (int j4 = 0; j4 < 16; j4++) {
                float4 vv = sv[c][j4];
                a += s[4 * j4 + 0] * vv.x;
                a += s[4 * j4 + 1] * vv.y;
                a += s[4 * j4 + 2] * vv.z;
                a += s[4 * j4 + 3] * vv.w;
            }
            acc[c] = a;
        }
    }

    float invl = 1.f / l;
#pragma unroll
    for (int c = 0; c < HD; c++)
        att[((size_t)b * CDIM + h * HD + c) * HWDIM + qi] = acc[c] * invl;
}

// ---------------------------------------------------------------------------
// Launch
// ---------------------------------------------------------------------------
extern "C" void kernel_launch(void* const* d_in, const int* in_sizes, int n_in,
                              void* d_out, int out_size) {
    const float* x      = (const float*)d_in[0];
    const float* gn_w   = (const float*)d_in[1];
    const float* gn_b   = (const float*)d_in[2];
    const float* qkv_w  = (const float*)d_in[3];
    const float* qkv_b  = (const float*)d_in[4];
    const float* proj_w = (const float*)d_in[5];
    const float* proj_b = (const float*)d_in[6];
    float* out = (float*)d_out;

    float *xn_p, *qkv_p, *att_p;
    cudaGetSymbolAddress((void**)&xn_p, g_xn);
    cudaGetSymbolAddress((void**)&qkv_p, g_qkv);
    cudaGetSymbolAddress((void**)&att_p, g_att);

    // 1. GN stats
    gn_stats_kernel<<<BATCH * NGROUP, 256>>>(x);
    // 2. GN apply
    gn_apply_kernel<<<(BATCH * CDIM * HWDIM / 4 + 255) / 256, 256>>>(x, gn_w, gn_b);
    // 3. QKV GEMM: (384 x 128) @ (128 x 4096) per batch
    gemm_kernel<OC, false><<<dim3(HWDIM / 64, OC / 64, BATCH), 256>>>(
        qkv_w, qkv_b, xn_p, qkv_p, nullptr);
    // 4. Attention
    attn_kernel<<<dim3(HWDIM / 128, NH, BATCH), 128>>>(qkv_p, att_p);
    // 5. Projection + bias + residual
    gemm_kernel<CDIM, true><<<dim3(HWDIM / 64, CDIM / 64, BATCH), 256>>>(
        proj_w, proj_b, att_p, out, xn_p);
}

// round 2
// speedup vs baseline: 2.4043x; 2.4043x over previous
#include <cuda_runtime.h>
#include <math.h>

#define BATCH 4
#define CDIM 128
#define HWDIM 4096
#define NGROUP 8
#define CPG 16
#define NH 4
#define HD 32
#define OC 384   // 3*C

// Scratch (allocation-free: device globals)
__device__ float g_xn[BATCH * CDIM * HWDIM];    // 8 MB  groupnorm output (also residual)
__device__ float g_qkv[BATCH * OC * HWDIM];     // 24 MB qkv projections
__device__ float g_att[BATCH * CDIM * HWDIM];   // 8 MB  attention output
__device__ float g_mean[BATCH * NGROUP];
__device__ float g_rstd[BATCH * NGROUP];

__device__ __forceinline__ float to_tf32(float x) {
    float r;
    asm("cvt.rna.tf32.f32 %0, %1;" : "=f"(r) : "f"(x));
    return r;
}

__device__ __forceinline__ void mma8(float* d, const unsigned* a, unsigned b0, unsigned b1) {
    asm volatile(
        "mma.sync.aligned.m16n8k8.row.col.f32.tf32.tf32.f32 "
        "{%0,%1,%2,%3},{%4,%5,%6,%7},{%8,%9},{%0,%1,%2,%3};\n"
        : "+f"(d[0]), "+f"(d[1]), "+f"(d[2]), "+f"(d[3])
        : "r"(a[0]), "r"(a[1]), "r"(a[2]), "r"(a[3]), "r"(b0), "r"(b1));
}

// ---------------------------------------------------------------------------
// 1. GroupNorm statistics
// ---------------------------------------------------------------------------
__global__ void gn_stats_kernel(const float* __restrict__ x) {
    int bg = blockIdx.x;
    const float4* p = reinterpret_cast<const float4*>(x + (size_t)bg * CPG * HWDIM);
    const int n4 = CPG * HWDIM / 4;
    float s = 0.f, ss = 0.f;
    for (int i = threadIdx.x; i < n4; i += blockDim.x) {
        float4 v = p[i];
        s  += v.x + v.y + v.z + v.w;
        ss += v.x * v.x + v.y * v.y + v.z * v.z + v.w * v.w;
    }
    __shared__ float sh_s[256], sh_ss[256];
    sh_s[threadIdx.x] = s;
    sh_ss[threadIdx.x] = ss;
    __syncthreads();
    for (int off = 128; off > 0; off >>= 1) {
        if (threadIdx.x < off) {
            sh_s[threadIdx.x]  += sh_s[threadIdx.x + off];
            sh_ss[threadIdx.x] += sh_ss[threadIdx.x + off];
        }
        __syncthreads();
    }
    if (threadIdx.x == 0) {
        const float inv = 1.0f / (float)(CPG * HWDIM);
        float mean = sh_s[0] * inv;
        float var  = sh_ss[0] * inv - mean * mean;
        g_mean[bg] = mean;
        g_rstd[bg] = rsqrtf(var + 1e-5f);
    }
}

// ---------------------------------------------------------------------------
// 2. Apply GroupNorm
// ---------------------------------------------------------------------------
__global__ void gn_apply_kernel(const float* __restrict__ x,
                                const float* __restrict__ w,
                                const float* __restrict__ bias) {
    int i4 = blockIdx.x * blockDim.x + threadIdx.x;
    const int total4 = BATCH * CDIM * HWDIM / 4;
    if (i4 >= total4) return;
    int e  = i4 * 4;
    int c  = (e / HWDIM) % CDIM;
    int bg = e / (CPG * HWDIM);
    float mean = g_mean[bg], rstd = g_rstd[bg];
    float sw = w[c] * rstd;
    float sb = bias[c] - mean * sw;
    float4 v = reinterpret_cast<const float4*>(x)[i4];
    float4 o;
    o.x = v.x * sw + sb;
    o.y = v.y * sw + sb;
    o.z = v.z * sw + sb;
    o.w = v.w * sw + sb;
    reinterpret_cast<float4*>(g_xn)[i4] = o;
}

// ---------------------------------------------------------------------------
// 3/5. Batched GEMM (fp32 SIMT): Out[b,o,t] = sum_c W[o,c]*X[b,c,t] + bias (+resid)
// ---------------------------------------------------------------------------
template <int OTOT, bool RESID>
__global__ void __launch_bounds__(256) gemm_kernel(const float* __restrict__ W,
                                                   const float* __restrict__ bias,
                                                   const float* __restrict__ X,
                                                   float* __restrict__ Out,
                                                   const float* __restrict__ resid) {
    int b = blockIdx.z;
    const float* Xb = X + (size_t)b * CDIM * HWDIM;
    float* Ob = Out + (size_t)b * OTOT * HWDIM;
    int o0 = blockIdx.y * 64;
    int t0 = blockIdx.x * 64;
    __shared__ float As[16][64];
    __shared__ float Bs[16][68];
    float acc[4][4];
#pragma unroll
    for (int i = 0; i < 4; i++)
#pragma unroll
        for (int j = 0; j < 4; j++) acc[i][j] = 0.f;

    int tid = threadIdx.x;
    int tx = tid & 15, ty = tid >> 4;

    for (int k0 = 0; k0 < CDIM; k0 += 16) {
#pragma unroll 4
        for (int i = tid; i < 64 * 16; i += 256) {
            int o = i >> 4, k = i & 15;
            As[k][o] = W[(size_t)(o0 + o) * CDIM + k0 + k];
        }
#pragma unroll 4
        for (int i = tid; i < 16 * 64; i += 256) {
            int k = i >> 6, t = i & 63;
            Bs[k][t] = Xb[(size_t)(k0 + k) * HWDIM + t0 + t];
        }
        __syncthreads();
#pragma unroll
        for (int k = 0; k < 16; k++) {
            float a[4], bb[4];
#pragma unroll
            for (int i = 0; i < 4; i++) a[i] = As[k][ty * 4 + i];
#pragma unroll
            for (int j = 0; j < 4; j++) bb[j] = Bs[k][tx * 4 + j];
#pragma unroll
            for (int i = 0; i < 4; i++)
#pragma unroll
                for (int j = 0; j < 4; j++) acc[i][j] += a[i] * bb[j];
        }
        __syncthreads();
    }

#pragma unroll
    for (int i = 0; i < 4; i++) {
        int o = o0 + ty * 4 + i;
        float bo = bias[o];
#pragma unroll
        for (int j = 0; j < 4; j++) {
            int t = t0 + tx * 4 + j;
            float v = acc[i][j] + bo;
            if (RESID) v += resid[(size_t)b * CDIM * HWDIM + (size_t)o * HWDIM + t];
            Ob[(size_t)o * HWDIM + t] = v;
        }
    }
}

// ---------------------------------------------------------------------------
// 4. Flash attention with tf32 mma.sync (tensor pipe).
//    One CTA = 128 queries for one (b,h). 4 warps x 32 queries.
//    Key tiles of 64. Q,K,V,P all tf32 in smem; fp32 accumulate.
//    Layouts: q_s[query][ch], k_s[ch][key], v_s[ch][key], p_s[query][key].
// ---------------------------------------------------------------------------
#define QS_LD 36
#define KS_LD 68
#define PS_LD 68
#define ATTN_SMEM_FLOATS (128 * QS_LD + 32 * KS_LD + 32 * KS_LD + 128 * PS_LD)

__global__ void __launch_bounds__(128) attn_mma_kernel(const float* __restrict__ qkv,
                                                       float* __restrict__ att) {
    extern __shared__ float smem[];
    float (*q_s)[QS_LD] = (float(*)[QS_LD])smem;
    float (*k_s)[KS_LD] = (float(*)[KS_LD])(smem + 128 * QS_LD);
    float (*v_s)[KS_LD] = (float(*)[KS_LD])(smem + 128 * QS_LD + 32 * KS_LD);
    float (*p_s)[PS_LD] = (float(*)[PS_LD])(smem + 128 * QS_LD + 64 * KS_LD);

    const int b = blockIdx.z, h = blockIdx.y;
    const int q0 = blockIdx.x * 128;
    const int tid = threadIdx.x;
    const int warp = tid >> 5, lane = tid & 31;
    const int lr = lane >> 2;   // row-within-frag (0..7)
    const int lc = lane & 3;    // col-group (0..3)

    const float* Qb = qkv + ((size_t)b * OC + h * HD) * HWDIM;
    const float* Kb = Qb + (size_t)CDIM * HWDIM;
    const float* Vb = Qb + (size_t)2 * CDIM * HWDIM;
    const float scale = 0.088388347648318447f;  // 128^-0.5

    // Load + scale + tf32-convert Q tile [128 q][32 ch]
    for (int i = tid; i < 32 * 128; i += 128) {
        int ch = i >> 7, qq = i & 127;
        q_s[qq][ch] = to_tf32(Qb[(size_t)ch * HWDIM + q0 + qq] * scale);
    }
    __syncthreads();

    // Q fragments in registers: qa[mfrag][kstep][4]
    unsigned qa[2][4][4];
#pragma unroll
    for (int mf = 0; mf < 2; mf++) {
        int r0 = warp * 32 + mf * 16 + lr;
#pragma unroll
        for (int kk = 0; kk < 4; kk++) {
            int c0 = kk * 8 + lc;
            qa[mf][kk][0] = __float_as_uint(q_s[r0][c0]);
            qa[mf][kk][1] = __float_as_uint(q_s[r0 + 8][c0]);
            qa[mf][kk][2] = __float_as_uint(q_s[r0][c0 + 4]);
            qa[mf][kk][3] = __float_as_uint(q_s[r0 + 8][c0 + 4]);
        }
    }

    float m_i[4], l_i[4];
    float oacc[2][4][4];
#pragma unroll
    for (int i = 0; i < 4; i++) { m_i[i] = -1e30f; l_i[i] = 0.f; }
#pragma unroll
    for (int mf = 0; mf < 2; mf++)
#pragma unroll
        for (int nf = 0; nf < 4; nf++)
#pragma unroll
            for (int c = 0; c < 4; c++) oacc[mf][nf][c] = 0.f;

    for (int j0 = 0; j0 < HWDIM; j0 += 64) {
        __syncthreads();  // previous tile's v_s reads done
        for (int i = tid; i < 32 * 64; i += 128) {
            int ch = i >> 6, j = i & 63;
            k_s[ch][j] = to_tf32(Kb[(size_t)ch * HWDIM + j0 + j]);
            v_s[ch][j] = to_tf32(Vb[(size_t)ch * HWDIM + j0 + j]);
        }
        __syncthreads();

        // S = Q @ K : sacc[mfrag][nfrag][4], 32q x 64k per warp
        float sacc[2][8][4];
#pragma unroll
        for (int mf = 0; mf < 2; mf++)
#pragma unroll
            for (int nf = 0; nf < 8; nf++)
#pragma unroll
                for (int c = 0; c < 4; c++) sacc[mf][nf][c] = 0.f;

#pragma unroll
        for (int kk = 0; kk < 4; kk++) {
#pragma unroll
            for (int nf = 0; nf < 8; nf++) {
                unsigned b0 = __float_as_uint(k_s[kk * 8 + lc][nf * 8 + lr]);
                unsigned b1 = __float_as_uint(k_s[kk * 8 + lc + 4][nf * 8 + lr]);
                mma8(sacc[0][nf], qa[0][kk], b0, b1);
                mma8(sacc[1][nf], qa[1][kk], b0, b1);
            }
        }

        // Online softmax (per row; each row shared by lanes lc=0..3)
#pragma unroll
        for (int mf = 0; mf < 2; mf++) {
#pragma unroll
            for (int ri = 0; ri < 2; ri++) {
                int rs = mf * 2 + ri;
                float mx = -1e30f;
#pragma unroll
                for (int nf = 0; nf < 8; nf++)
                    mx = fmaxf(mx, fmaxf(sacc[mf][nf][2 * ri], sacc[mf][nf][2 * ri + 1]));
                mx = fmaxf(mx, __shfl_xor_sync(0xffffffffu, mx, 1));
                mx = fmaxf(mx, __shfl_xor_sync(0xffffffffu, mx, 2));
                float newm = fmaxf(m_i[rs], mx);
                float corr = __expf(m_i[rs] - newm);
                m_i[rs] = newm;
                float sum = 0.f;
#pragma unroll
                for (int nf = 0; nf < 8; nf++) {
                    float p0 = __expf(sacc[mf][nf][2 * ri] - newm);
                    float p1 = __expf(sacc[mf][nf][2 * ri + 1] - newm);
                    sacc[mf][nf][2 * ri] = p0;
                    sacc[mf][nf][2 * ri + 1] = p1;
                    sum += p0 + p1;
                }
                sum += __shfl_xor_sync(0xffffffffu, sum, 1);
                sum += __shfl_xor_sync(0xffffffffu, sum, 2);
                l_i[rs] = l_i[rs] * corr + sum;
#pragma unroll
                for (int nf = 0; nf < 4; nf++) {
                    oacc[mf][nf][2 * ri] *= corr;
                    oacc[mf][nf][2 * ri + 1] *= corr;
                }
            }
        }

        // Store P (tf32) to smem for A-operand reload
#pragma unroll
        for (int mf = 0; mf < 2; mf++) {
            int r0 = warp * 32 + mf * 16 + lr;
#pragma unroll
            for (int nf = 0; nf < 8; nf++) {
                int col = nf * 8 + 2 * lc;
                float2 s0 = make_float2(to_tf32(sacc[mf][nf][0]), to_tf32(sacc[mf][nf][1]));
                float2 s1 = make_float2(to_tf32(sacc[mf][nf][2]), to_tf32(sacc[mf][nf][3]));
                *(float2*)&p_s[r0][col]     = s0;
                *(float2*)&p_s[r0 + 8][col] = s1;
            }
        }
        __syncwarp();

        // O += P @ V^T : A = P [32q x 64k], B = V (k x ch) from v_s[ch][key]
#pragma unroll
        for (int kk = 0; kk < 8; kk++) {
            unsigned pa[2][4];
#pragma unroll
            for (int mf = 0; mf < 2; mf++) {
                int r0 = warp * 32 + mf * 16 + lr;
                int c0 = kk * 8 + lc;
                pa[mf][0] = __float_as_uint(p_s[r0][c0]);
                pa[mf][1] = __float_as_uint(p_s[r0 + 8][c0]);
                pa[mf][2] = __float_as_uint(p_s[r0][c0 + 4]);
                pa[mf][3] = __float_as_uint(p_s[r0 + 8][c0 + 4]);
            }
#pragma unroll
            for (int nf = 0; nf < 4; nf++) {
                unsigned b0 = __float_as_uint(v_s[nf * 8 + lr][kk * 8 + lc]);
                unsigned b1 = __float_as_uint(v_s[nf * 8 + lr][kk * 8 + lc + 4]);
                mma8(oacc[0][nf], pa[0], b0, b1);
                mma8(oacc[1][nf], pa[1], b0, b1);
            }
        }
    }

    // Epilogue: divide by l, write out (att layout [ch][token])
#pragma unroll
    for (int mf = 0; mf < 2; mf++) {
#pragma unroll
        for (int ri = 0; ri < 2; ri++) {
            float inv = 1.f / l_i[mf * 2 + ri];
            int q = q0 + warp * 32 + mf * 16 + lr + ri * 8;
#pragma unroll
            for (int nf = 0; nf < 4; nf++) {
#pragma unroll
                for (int c = 0; c < 2; c++) {
                    int ch = nf * 8 + 2 * lc + c;
                    att[((size_t)b * CDIM + h * HD + ch) * HWDIM + q] =
                        oacc[mf][nf][2 * ri + c] * inv;
                }
            }
        }
    }
}

// ---------------------------------------------------------------------------
// Launch
// ---------------------------------------------------------------------------
extern "C" void kernel_launch(void* const* d_in, const int* in_sizes, int n_in,
                              void* d_out, int out_size) {
    const float* x      = (const float*)d_in[0];
    const float* gn_w   = (const float*)d_in[1];
    const float* gn_b   = (const float*)d_in[2];
    const float* qkv_w  = (const float*)d_in[3];
    const float* qkv_b  = (const float*)d_in[4];
    const float* proj_w = (const float*)d_in[5];
    const float* proj_b = (const float*)d_in[6];
    float* out = (float*)d_out;

    float *xn_p, *qkv_p, *att_p;
    cudaGetSymbolAddress((void**)&xn_p, g_xn);
    cudaGetSymbolAddress((void**)&qkv_p, g_qkv);
    cudaGetSymbolAddress((void**)&att_p, g_att);

    static bool attr_set = false;
    if (!attr_set) {
        cudaFuncSetAttribute(attn_mma_kernel,
                             cudaFuncAttributeMaxDynamicSharedMemorySize,
                             ATTN_SMEM_FLOATS * (int)sizeof(float));
        attr_set = true;
    }

    gn_stats_kernel<<<BATCH * NGROUP, 256>>>(x);
    gn_apply_kernel<<<(BATCH * CDIM * HWDIM / 4 + 255) / 256, 256>>>(x, gn_w, gn_b);
    gemm_kernel<OC, false><<<dim3(HWDIM / 64, OC / 64, BATCH), 256>>>(
        qkv_w, qkv_b, xn_p, qkv_p, nullptr);
    attn_mma_kernel<<<dim3(HWDIM / 128, NH, BATCH), 128,
                      ATTN_SMEM_FLOATS * (int)sizeof(float)>>>(qkv_p, att_p);
    gemm_kernel<CDIM, true><<<dim3(HWDIM / 64, CDIM / 64, BATCH), 256>>>(
        proj_w, proj_b, att_p, out, xn_p);
}

// round 3
// speedup vs baseline: 2.5083x; 1.0432x over previous
#include <cuda_runtime.h>
#include <math.h>

#define BATCH 4
#define CDIM 128
#define HWDIM 4096
#define NGROUP 8
#define CPG 16
#define NH 4
#define HD 32
#define OC 384   // 3*C

// Scratch (allocation-free: device globals)
__device__ float g_xn[BATCH * CDIM * HWDIM];    // 8 MB  groupnorm output (also residual)
__device__ float g_qkv[BATCH * OC * HWDIM];     // 24 MB qkv projections
__device__ float g_att[BATCH * CDIM * HWDIM];   // 8 MB  attention output
__device__ float g_mean[BATCH * NGROUP];
__device__ float g_rstd[BATCH * NGROUP];

__device__ __forceinline__ void mma8(float* d, const unsigned* a, unsigned b0, unsigned b1) {
    asm volatile(
        "mma.sync.aligned.m16n8k8.row.col.f32.tf32.tf32.f32 "
        "{%0,%1,%2,%3},{%4,%5,%6,%7},{%8,%9},{%0,%1,%2,%3};\n"
        : "+f"(d[0]), "+f"(d[1]), "+f"(d[2]), "+f"(d[3])
        : "r"(a[0]), "r"(a[1]), "r"(a[2]), "r"(a[3]), "r"(b0), "r"(b1));
}

// ---------------------------------------------------------------------------
// 1. GroupNorm statistics
// ---------------------------------------------------------------------------
__global__ void gn_stats_kernel(const float* __restrict__ x) {
    int bg = blockIdx.x;
    const float4* p = reinterpret_cast<const float4*>(x + (size_t)bg * CPG * HWDIM);
    const int n4 = CPG * HWDIM / 4;
    float s = 0.f, ss = 0.f;
    for (int i = threadIdx.x; i < n4; i += blockDim.x) {
        float4 v = p[i];
        s  += v.x + v.y + v.z + v.w;
        ss += v.x * v.x + v.y * v.y + v.z * v.z + v.w * v.w;
    }
    __shared__ float sh_s[256], sh_ss[256];
    sh_s[threadIdx.x] = s;
    sh_ss[threadIdx.x] = ss;
    __syncthreads();
    for (int off = 128; off > 0; off >>= 1) {
        if (threadIdx.x < off) {
            sh_s[threadIdx.x]  += sh_s[threadIdx.x + off];
            sh_ss[threadIdx.x] += sh_ss[threadIdx.x + off];
        }
        __syncthreads();
    }
    if (threadIdx.x == 0) {
        const float inv = 1.0f / (float)(CPG * HWDIM);
        float mean = sh_s[0] * inv;
        float var  = sh_ss[0] * inv - mean * mean;
        g_mean[bg] = mean;
        g_rstd[bg] = rsqrtf(var + 1e-5f);
    }
}

// ---------------------------------------------------------------------------
// 2. Apply GroupNorm
// ---------------------------------------------------------------------------
__global__ void gn_apply_kernel(const float* __restrict__ x,
                                const float* __restrict__ w,
                                const float* __restrict__ bias) {
    int i4 = blockIdx.x * blockDim.x + threadIdx.x;
    const int total4 = BATCH * CDIM * HWDIM / 4;
    if (i4 >= total4) return;
    int e  = i4 * 4;
    int c  = (e / HWDIM) % CDIM;
    int bg = e / (CPG * HWDIM);
    float mean = g_mean[bg], rstd = g_rstd[bg];
    float sw = w[c] * rstd;
    float sb = bias[c] - mean * sw;
    float4 v = reinterpret_cast<const float4*>(x)[i4];
    float4 o;
    o.x = v.x * sw + sb;
    o.y = v.y * sw + sb;
    o.z = v.z * sw + sb;
    o.w = v.w * sw + sb;
    reinterpret_cast<float4*>(g_xn)[i4] = o;
}

// ---------------------------------------------------------------------------
// 3/5. Batched GEMM (fp32 SIMT)
// ---------------------------------------------------------------------------
template <int OTOT, bool RESID>
__global__ void __launch_bounds__(256) gemm_kernel(const float* __restrict__ W,
                                                   const float* __restrict__ bias,
                                                   const float* __restrict__ X,
                                                   float* __restrict__ Out,
                                                   const float* __restrict__ resid) {
    int b = blockIdx.z;
    const float* Xb = X + (size_t)b * CDIM * HWDIM;
    float* Ob = Out + (size_t)b * OTOT * HWDIM;
    int o0 = blockIdx.y * 64;
    int t0 = blockIdx.x * 64;
    __shared__ float As[16][64];
    __shared__ float Bs[16][68];
    float acc[4][4];
#pragma unroll
    for (int i = 0; i < 4; i++)
#pragma unroll
        for (int j = 0; j < 4; j++) acc[i][j] = 0.f;

    int tid = threadIdx.x;
    int tx = tid & 15, ty = tid >> 4;

    for (int k0 = 0; k0 < CDIM; k0 += 16) {
#pragma unroll 4
        for (int i = tid; i < 64 * 16; i += 256) {
            int o = i >> 4, k = i & 15;
            As[k][o] = W[(size_t)(o0 + o) * CDIM + k0 + k];
        }
#pragma unroll 4
        for (int i = tid; i < 16 * 64; i += 256) {
            int k = i >> 6, t = i & 63;
            Bs[k][t] = Xb[(size_t)(k0 + k) * HWDIM + t0 + t];
        }
        __syncthreads();
#pragma unroll
        for (int k = 0; k < 16; k++) {
            float a[4], bb[4];
#pragma unroll
            for (int i = 0; i < 4; i++) a[i] = As[k][ty * 4 + i];
#pragma unroll
            for (int j = 0; j < 4; j++) bb[j] = Bs[k][tx * 4 + j];
#pragma unroll
            for (int i = 0; i < 4; i++)
#pragma unroll
                for (int j = 0; j < 4; j++) acc[i][j] += a[i] * bb[j];
        }
        __syncthreads();
    }

#pragma unroll
    for (int i = 0; i < 4; i++) {
        int o = o0 + ty * 4 + i;
        float bo = bias[o];
#pragma unroll
        for (int j = 0; j < 4; j++) {
            int t = t0 + tx * 4 + j;
            float v = acc[i][j] + bo;
            if (RESID) v += resid[(size_t)b * CDIM * HWDIM + (size_t)o * HWDIM + t];
            Ob[(size_t)o * HWDIM + t] = v;
        }
    }
}

// ---------------------------------------------------------------------------
// 4. Flash attention, tf32 mma. 128q per CTA, 4 warps x 32q, 64-key tiles.
//    smem: region A = q_s[128][36] reused as p_s[128][36] (P in 32-key halves)
//          region B = k_s[32][68], v_s[32][68]
//    fp32 operands fed raw to tf32 mma (HW truncation). exp2-domain softmax.
// ---------------------------------------------------------------------------
#define QS_LD 36
#define KS_LD 68
#define SMEM_A_FLOATS (128 * QS_LD)
#define SMEM_B_FLOATS (2 * 32 * KS_LD)
#define ATTN_SMEM_FLOATS (SMEM_A_FLOATS + SMEM_B_FLOATS)

__global__ void __launch_bounds__(128) attn_mma_kernel(const float* __restrict__ qkv,
                                                       float* __restrict__ att) {
    extern __shared__ float smem[];
    float (*q_s)[QS_LD] = (float(*)[QS_LD])smem;               // phase 1
    float (*p_s)[QS_LD] = (float(*)[QS_LD])smem;               // phase 2 (same space)
    float (*k_s)[KS_LD] = (float(*)[KS_LD])(smem + SMEM_A_FLOATS);
    float (*v_s)[KS_LD] = (float(*)[KS_LD])(smem + SMEM_A_FLOATS + 32 * KS_LD);

    const int b = blockIdx.z, h = blockIdx.y;
    const int q0 = blockIdx.x * 128;
    const int tid = threadIdx.x;
    const int warp = tid >> 5, lane = tid & 31;
    const int lr = lane >> 2;   // 0..7
    const int lc = lane & 3;    // 0..3

    const float* Qb = qkv + ((size_t)b * OC + h * HD) * HWDIM;
    const float* Kb = Qb + (size_t)CDIM * HWDIM;
    const float* Vb = Qb + (size_t)2 * CDIM * HWDIM;
    // 128^-0.5 * log2(e): softmax runs in exp2 domain
    const float scale = 0.088388347648318447f * 1.4426950408889634f;

    // Load + scale Q tile [128 q][32 ch]
    for (int i = tid; i < 32 * 128; i += 128) {
        int ch = i >> 7, qq = i & 127;
        q_s[qq][ch] = Qb[(size_t)ch * HWDIM + q0 + qq] * scale;
    }
    __syncthreads();

    // Q fragments: qa[mfrag][kstep][4]
    unsigned qa[2][4][4];
#pragma unroll
    for (int mf = 0; mf < 2; mf++) {
        int r0 = warp * 32 + mf * 16 + lr;
#pragma unroll
        for (int kk = 0; kk < 4; kk++) {
            int c0 = kk * 8 + lc;
            qa[mf][kk][0] = __float_as_uint(q_s[r0][c0]);
            qa[mf][kk][1] = __float_as_uint(q_s[r0 + 8][c0]);
            qa[mf][kk][2] = __float_as_uint(q_s[r0][c0 + 4]);
            qa[mf][kk][3] = __float_as_uint(q_s[r0 + 8][c0 + 4]);
        }
    }
    __syncthreads();  // q_s fully consumed; space becomes p_s

    float m_i[4], l_i[4];
    float oacc[2][4][4];
#pragma unroll
    for (int i = 0; i < 4; i++) { m_i[i] = -1e30f; l_i[i] = 0.f; }
#pragma unroll
    for (int mf = 0; mf < 2; mf++)
#pragma unroll
        for (int nf = 0; nf < 4; nf++)
#pragma unroll
            for (int c = 0; c < 4; c++) oacc[mf][nf][c] = 0.f;

    for (int j0 = 0; j0 < HWDIM; j0 += 64) {
        __syncthreads();  // previous tile k/v reads done
        for (int i = tid; i < 32 * 64; i += 128) {
            int ch = i >> 6, j = i & 63;
            k_s[ch][j] = Kb[(size_t)ch * HWDIM + j0 + j];
            v_s[ch][j] = Vb[(size_t)ch * HWDIM + j0 + j];
        }
        __syncthreads();

        // S = Q @ K^T (exp2-domain scores): 32q x 64k per warp
        float sacc[2][8][4];
#pragma unroll
        for (int mf = 0; mf < 2; mf++)
#pragma unroll
            for (int nf = 0; nf < 8; nf++)
#pragma unroll
                for (int c = 0; c < 4; c++) sacc[mf][nf][c] = 0.f;

#pragma unroll
        for (int kk = 0; kk < 4; kk++) {
#pragma unroll
            for (int nf = 0; nf < 8; nf++) {
                unsigned b0 = __float_as_uint(k_s[kk * 8 + lc][nf * 8 + lr]);
                unsigned b1 = __float_as_uint(k_s[kk * 8 + lc + 4][nf * 8 + lr]);
                mma8(sacc[0][nf], qa[0][kk], b0, b1);
                mma8(sacc[1][nf], qa[1][kk], b0, b1);
            }
        }

        // Online softmax (exp2 domain)
#pragma unroll
        for (int mf = 0; mf < 2; mf++) {
#pragma unroll
            for (int ri = 0; ri < 2; ri++) {
                int rs = mf * 2 + ri;
                float mx = -1e30f;
#pragma unroll
                for (int nf = 0; nf < 8; nf++)
                    mx = fmaxf(mx, fmaxf(sacc[mf][nf][2 * ri], sacc[mf][nf][2 * ri + 1]));
                mx = fmaxf(mx, __shfl_xor_sync(0xffffffffu, mx, 1));
                mx = fmaxf(mx, __shfl_xor_sync(0xffffffffu, mx, 2));
                float newm = fmaxf(m_i[rs], mx);
                float corr = exp2f(m_i[rs] - newm);
                m_i[rs] = newm;
                float sum = 0.f;
#pragma unroll
                for (int nf = 0; nf < 8; nf++) {
                    float p0 = exp2f(sacc[mf][nf][2 * ri] - newm);
                    float p1 = exp2f(sacc[mf][nf][2 * ri + 1] - newm);
                    sacc[mf][nf][2 * ri] = p0;
                    sacc[mf][nf][2 * ri + 1] = p1;
                    sum += p0 + p1;
                }
                sum += __shfl_xor_sync(0xffffffffu, sum, 1);
                sum += __shfl_xor_sync(0xffffffffu, sum, 2);
                l_i[rs] = l_i[rs] * corr + sum;
#pragma unroll
                for (int nf = 0; nf < 4; nf++) {
                    oacc[mf][nf][2 * ri] *= corr;
                    oacc[mf][nf][2 * ri + 1] *= corr;
                }
            }
        }

        // O += P @ V in two 32-key halves through per-warp smem scratch
#pragma unroll
        for (int half = 0; half < 2; half++) {
            __syncwarp();  // previous half's P loads done
#pragma unroll
            for (int mf = 0; mf < 2; mf++) {
                int r0 = warp * 32 + mf * 16 + lr;
#pragma unroll
                for (int nf = 0; nf < 4; nf++) {
                    int nfg = half * 4 + nf;
                    int col = nf * 8 + 2 * lc;
                    *(float2*)&p_s[r0][col] =
                        make_float2(sacc[mf][nfg][0], sacc[mf][nfg][1]);
                    *(float2*)&p_s[r0 + 8][col] =
                        make_float2(sacc[mf][nfg][2], sacc[mf][nfg][3]);
                }
            }
            __syncwarp();
#pragma unroll
            for (int kk = 0; kk < 4; kk++) {
                unsigned pa[2][4];
#pragma unroll
                for (int mf = 0; mf < 2; mf++) {
                    int r0 = warp * 32 + mf * 16 + lr;
                    int c0 = kk * 8 + lc;
                    pa[mf][0] = __float_as_uint(p_s[r0][c0]);
                    pa[mf][1] = __float_as_uint(p_s[r0 + 8][c0]);
                    pa[mf][2] = __float_as_uint(p_s[r0][c0 + 4]);
                    pa[mf][3] = __float_as_uint(p_s[r0 + 8][c0 + 4]);
                }
                int key0 = half * 32 + kk * 8;
#pragma unroll
                for (int nf = 0; nf < 4; nf++) {
                    unsigned b0 = __float_as_uint(v_s[nf * 8 + lr][key0 + lc]);
                    unsigned b1 = __float_as_uint(v_s[nf * 8 + lr][key0 + lc + 4]);
                    mma8(oacc[0][nf], pa[0], b0, b1);
                    mma8(oacc[1][nf], pa[1], b0, b1);
                }
            }
        }
    }

    // Epilogue
#pragma unroll
    for (int mf = 0; mf < 2; mf++) {
#pragma unroll
        for (int ri = 0; ri < 2; ri++) {
            float inv = 1.f / l_i[mf * 2 + ri];
            int q = q0 + warp * 32 + mf * 16 + lr + ri * 8;
#pragma unroll
            for (int nf = 0; nf < 4; nf++) {
#pragma unroll
                for (int c = 0; c < 2; c++) {
                    int ch = nf * 8 + 2 * lc + c;
                    att[((size_t)b * CDIM + h * HD + ch) * HWDIM + q] =
                        oacc[mf][nf][2 * ri + c] * inv;
                }
            }
        }
    }
}

// ---------------------------------------------------------------------------
// Launch
// ---------------------------------------------------------------------------
extern "C" void kernel_launch(void* const* d_in, const int* in_sizes, int n_in,
                              void* d_out, int out_size) {
    const float* x      = (const float*)d_in[0];
    const float* gn_w   = (const float*)d_in[1];
    const float* gn_b   = (const float*)d_in[2];
    const float* qkv_w  = (const float*)d_in[3];
    const float* qkv_b  = (const float*)d_in[4];
    const float* proj_w = (const float*)d_in[5];
    const float* proj_b = (const float*)d_in[6];
    float* out = (float*)d_out;

    float *xn_p, *qkv_p, *att_p;
    cudaGetSymbolAddress((void**)&xn_p, g_xn);
    cudaGetSymbolAddress((void**)&qkv_p, g_qkv);
    cudaGetSymbolAddress((void**)&att_p, g_att);

    static bool attr_set = false;
    if (!attr_set) {
        cudaFuncSetAttribute(attn_mma_kernel,
                             cudaFuncAttributeMaxDynamicSharedMemorySize,
                             ATTN_SMEM_FLOATS * (int)sizeof(float));
        cudaFuncSetAttribute(attn_mma_kernel,
                             cudaFuncAttributePreferredSharedMemoryCarveout,
                             cudaSharedmemCarveoutMaxShared);
        attr_set = true;
    }

    gn_stats_kernel<<<BATCH * NGROUP, 256>>>(x);
    gn_apply_kernel<<<(BATCH * CDIM * HWDIM / 4 + 255) / 256, 256>>>(x, gn_w, gn_b);
    gemm_kernel<OC, false><<<dim3(HWDIM / 64, OC / 64, BATCH), 256>>>(
        qkv_w, qkv_b, xn_p, qkv_p, nullptr);
    attn_mma_kernel<<<dim3(HWDIM / 128, NH, BATCH), 128,
                      ATTN_SMEM_FLOATS * (int)sizeof(float)>>>(qkv_p, att_p);
    gemm_kernel<CDIM, true><<<dim3(HWDIM / 64, CDIM / 64, BATCH), 256>>>(
        proj_w, proj_b, att_p, out, xn_p);
}